// round 13
// baseline (speedup 1.0000x reference)
#include <cuda_runtime.h>

#define CIN 16
#define DIN 64
#define HIN 96
#define WIN 96
#define DD 32
#define HH 48
#define WW 48
#define NVOX (DD*HH*WW)          /* 73728 */
#define RR 3
#define PD (DD+2*RR)             /* 38 */
#define PH (HH+2*RR)             /* 54 */
#define PW (WW+2*RR)             /* 54 */
#define FMS 64                   /* padded row stride (float4) for g_fm */

#define N_FF (4*NVOX)
#define N_FM (4*PD*PH*PW)

// Pooled features. g_ff: ((z*HH+y)*4+q)*WW + x. g_fm zero-padded by RR each
// side, row stride padded to 64 float4 (aligned rows, shift addressing).
__device__ float4 g_ff[(size_t)DD*HH*4*WW];
__device__ __align__(256) float4 g_fm[(size_t)PD*PH*4*FMS];

// ---------------------------------------------------------------------------
// Fused pooling (both tensors, one grid) + zeroing of the output buffer.
// ---------------------------------------------------------------------------
__global__ void pool_kernel(const float* __restrict__ ff_in,
                            const float* __restrict__ fm_in,
                            float* __restrict__ out) {
    int i = blockIdx.x * blockDim.x + threadIdx.x;
    if (i < 2 * NVOX) out[i] = 0.0f;             // init output (scatter target)
    if (i < N_FF) {
        int x = i % WW;
        int y = (i / WW) % HH;
        int z = (i / (WW * HH)) % DD;
        int q = i / NVOX;
        float s[4];
#pragma unroll
        for (int cc = 0; cc < 4; cc++) {
            int c = q * 4 + cc;
            const float* p = ff_in + (((size_t)c * DIN + 2 * z) * HIN + 2 * y) * WIN + 2 * x;
            float acc = 0.f;
#pragma unroll
            for (int dz = 0; dz < 2; dz++)
#pragma unroll
                for (int dy = 0; dy < 2; dy++) {
                    const float2 v = *(const float2*)(p + (size_t)dz * HIN * WIN + dy * WIN);
                    acc += v.x + v.y;
                }
            s[cc] = acc * 0.125f;
        }
        g_ff[((size_t)(z * HH + y) * 4 + q) * WW + x] = make_float4(s[0], s[1], s[2], s[3]);
    } else {
        int j = i - N_FF;
        if (j >= N_FM) return;
        int x = j % PW;
        int y = (j / PW) % PH;
        int z = (j / (PW * PH)) % PD;
        int q = j / (PD * PH * PW);
        int iz = z - RR, iy = y - RR, ix = x - RR;
        float s[4] = {0.f, 0.f, 0.f, 0.f};
        if (iz >= 0 && iz < DD && iy >= 0 && iy < HH && ix >= 0 && ix < WW) {
#pragma unroll
            for (int cc = 0; cc < 4; cc++) {
                int c = q * 4 + cc;
                const float* p = fm_in + (((size_t)c * DIN + 2 * iz) * HIN + 2 * iy) * WIN + 2 * ix;
                float acc = 0.f;
#pragma unroll
                for (int dz = 0; dz < 2; dz++)
#pragma unroll
                    for (int dy = 0; dy < 2; dy++) {
                        const float2 v = *(const float2*)(p + (size_t)dz * HIN * WIN + dy * WIN);
                        acc += v.x + v.y;
                    }
                s[cc] = acc * 0.125f;
            }
        }
        g_fm[((size_t)(z * PH + y) * 4 + q) * FMS + x] = make_float4(s[0], s[1], s[2], s[3]);
    }
}

// ---------------------------------------------------------------------------
// Top-5 insertion (strict > keeps earliest window index on ties -> lax.top_k)
// ---------------------------------------------------------------------------
#define DEF_TOPK(P)                                                           \
    float P##v0 = -1e30f, P##v1 = -1e30f, P##v2 = -1e30f, P##v3 = -1e30f,     \
          P##v4 = -1e30f;                                                     \
    int P##q0 = 0, P##q1 = 0, P##q2 = 0, P##q3 = 0, P##q4 = 0;

#define TOPK_INS(P, cval, pidx)                                               \
    if (cval > P##v4) {                                                       \
        P##v4 = cval; P##q4 = pidx;                                           \
        if (P##v4 > P##v3) { float t = P##v4; P##v4 = P##v3; P##v3 = t;       \
                             int u = P##q4; P##q4 = P##q3; P##q3 = u; }       \
        if (P##v3 > P##v2) { float t = P##v3; P##v3 = P##v2; P##v2 = t;       \
                             int u = P##q3; P##q3 = P##q2; P##q2 = u; }       \
        if (P##v2 > P##v1) { float t = P##v2; P##v2 = P##v1; P##v1 = t;       \
                             int u = P##q2; P##q2 = P##q1; P##q1 = u; }       \
        if (P##v1 > P##v0) { float t = P##v1; P##v1 = P##v0; P##v0 = t;       \
                             int u = P##q1; P##q1 = P##q0; P##q0 = u; }       \
    }

// dot of 16-ch fixed features with moving features, sequential channel order
// (must stay sequential: matches reference summation, rel_err ~9e-8)
__device__ __forceinline__ float dot16(const float4& a0, const float4& a1,
                                       const float4& a2, const float4& a3,
                                       const float4& m0, const float4& m1,
                                       const float4& m2, const float4& m3) {
    float c = a0.x * m0.x;
    c = fmaf(a0.y, m0.y, c); c = fmaf(a0.z, m0.z, c); c = fmaf(a0.w, m0.w, c);
    c = fmaf(a1.x, m1.x, c); c = fmaf(a1.y, m1.y, c);
    c = fmaf(a1.z, m1.z, c); c = fmaf(a1.w, m1.w, c);
    c = fmaf(a2.x, m2.x, c); c = fmaf(a2.y, m2.y, c);
    c = fmaf(a2.z, m2.z, c); c = fmaf(a2.w, m2.w, c);
    c = fmaf(a3.x, m3.x, c); c = fmaf(a3.y, m3.y, c);
    c = fmaf(a3.z, m3.z, c); c = fmaf(a3.w, m3.w, c);
    return c;
}

// ---------------------------------------------------------------------------
// scatter one top-k winner into both output levels
// ---------------------------------------------------------------------------
__device__ __forceinline__ void scatter_one(float* __restrict__ out,
                                            int z, int y, int x,
                                            float v, int pj) {
    const float sc[4] = {1.0f, 0.5f, 0.25f, 0.125f};
    int oz = pj / 49 - 3;
    int oy = (pj / 7) % 7 - 3;
    int ox = pj % 7 - 3;

    // level 0: integer displacement, single unit-weight corner
    {
        int tz = min(max(z + oz, 0), DD - 1);
        int ty = min(max(y + oy, 0), HH - 1);
        int tx = min(max(x + ox, 0), WW - 1);
        atomicAdd(&out[(tz * HH + ty) * WW + tx], v);
    }
    // level 1: displacement * 0.5, trilinear splat
    {
        int fz = oz >> 1, fy = oy >> 1, fx = ox >> 1;   // floor(o/2)
        int ez = oz & 1, ey = oy & 1, ex = ox & 1;      // odd -> two corners
        float wv = v * sc[ez + ey + ex];
        float* out1 = out + NVOX;
#pragma unroll
        for (int cz = 0; cz < 2; cz++) {
            if (cz > ez) break;
            int tz = min(max(z + fz + cz, 0), DD - 1);
#pragma unroll
            for (int cy = 0; cy < 2; cy++) {
                if (cy > ey) break;
                int ty = min(max(y + fy + cy, 0), HH - 1);
#pragma unroll
                for (int cx = 0; cx < 2; cx++) {
                    if (cx > ex) break;
                    int tx = min(max(x + fx + cx, 0), WW - 1);
                    atomicAdd(&out1[(tz * HH + ty) * WW + tx], wv);
                }
            }
        }
    }
}

// merge 2 partial top-5 lists (10 smem entries) -> global top-5, then scatter.
// Tie-break: equal values -> smaller flat window index p (matches lax.top_k;
// partial lists cover disjoint ascending p-ranges so ties resolve by p).
__device__ __forceinline__ void merge_scatter10(const float* __restrict__ sv,
                                                const int* __restrict__ si,
                                                float* __restrict__ out,
                                                int z, int y, int x) {
    unsigned used = 0;
#pragma unroll
    for (int k = 0; k < 5; k++) {
        float best = -3e38f;
        int bestp = 0x7fffffff;
        int bi = 0;
#pragma unroll
        for (int i = 0; i < 10; i++) {
            if (used & (1u << i)) continue;
            float v = sv[i];
            int p = si[i];
            if (v > best || (v == best && p < bestp)) { best = v; bestp = p; bi = i; }
        }
        used |= 1u << bi;
        scatter_one(out, z, y, x, best, bestp);
    }
}

// ---------------------------------------------------------------------------
// Correlation + top-5 + scatter.  R9 skeleton (measured best: one voxel per
// thread, 49 window rows split 25/24 across a warp-pair, lanes -> 32
// consecutive x) with the inner loop restructured DOTS-THEN-INSERT:
//   phase 1: branch-free loop computes all 7 candidate dots of a row
//            (ptxas can software-pipeline all 28 LDG.128s -> high MLP)
//   phase 2: 7 branchy top-5 inserts with no loads trapped behind them
// Previously each candidate's branchy insert fenced the next candidate's
// loads into a separate basic block -> MLP~4 -> latency-bound at 50% issue.
// Bit-identical results: dot order and insert order unchanged.
// ---------------------------------------------------------------------------
__global__ void __launch_bounds__(128, 7) corr_scatter_kernel(float* __restrict__ out) {
    __shared__ float sv[2][32][10];
    __shared__ int   si[2][32][10];

    const int lane = threadIdx.x & 31;
    const int half = (threadIdx.x >> 5) & 1;     // which row-range of window
    const int set  = threadIdx.x >> 6;           // which 32-voxel group
    const int grp  = blockIdx.x * 64 + set * 32 + lane;  // exact grid: no guard
    const int x = grp % WW;
    const int y = (grp / WW) % HH;
    const int z = grp / (WW * HH);

    const float4* fa = &g_ff[((size_t)(z * HH + y) * 4) * WW + x];
    float4 a0 = fa[0], a1 = fa[WW], a2 = fa[2 * WW], a3 = fa[3 * WW];

    DEF_TOPK(A)

    const int r0 = half ? 25 : 0;                // rows 0-24 / 25-48 (175/168)
    const int r1 = half ? 49 : 25;
    for (int r = r0; r < r1; r++) {
        const int pz = r / 7;                    // const-div -> mul/shift
        const int py = r % 7;
        const float4* __restrict__ mb =
            &g_fm[((size_t)((z + pz) * PH + (y + py)) * 4) * FMS + x];
        const int rowp = r * 7;                  // p = pz*49 + py*7 + px

        // phase 1: branch-free dot computation (loads pipeline freely)
        float cv[7];
#pragma unroll
        for (int px = 0; px < 7; px++) {
            float4 m0 = mb[px];
            float4 m1 = mb[FMS + px];
            float4 m2 = mb[2 * FMS + px];
            float4 m3 = mb[3 * FMS + px];
            cv[px] = dot16(a0, a1, a2, a3, m0, m1, m2, m3);
        }
        // phase 2: branchy top-5 inserts (no loads behind these branches)
#pragma unroll
        for (int px = 0; px < 7; px++) {
            TOPK_INS(A, cv[px], rowp + px)
        }
    }

    // publish partial list (disjoint ascending p-ranges across halves)
    float* pv = &sv[set][lane][half * 5];
    int*   pi = &si[set][lane][half * 5];
    pv[0] = Av0; pv[1] = Av1; pv[2] = Av2; pv[3] = Av3; pv[4] = Av4;
    pi[0] = Aq0; pi[1] = Aq1; pi[2] = Aq2; pi[3] = Aq3; pi[4] = Aq4;

    __syncthreads();

    if (half == 0)
        merge_scatter10(&sv[set][lane][0], &si[set][lane][0], out, z, y, x);
}

// ---------------------------------------------------------------------------
extern "C" void kernel_launch(void* const* d_in, const int* in_sizes, int n_in,
                              void* d_out, int out_size) {
    (void)in_sizes; (void)n_in; (void)out_size;
    const float* feat_fix = (const float*)d_in[0];
    const float* feat_mov = (const float*)d_in[1];
    float* out = (float*)d_out;

    int t = 256;
    int pool_total = N_FF + N_FM;
    pool_kernel<<<(pool_total + t - 1) / t, t>>>(feat_fix, feat_mov, out);

    // 128 threads = 2 voxel-sets of 32 x 2 window-halves; NVOX/64 = 1152
    corr_scatter_kernel<<<NVOX / 64, 128>>>(out);
}